// round 8
// baseline (speedup 1.0000x reference)
#include <cuda_runtime.h>

#define B_ROWS 8192
#define P_ROWS 1024
#define D_DIM  256
#define NPART  16          // prototype partial-reduction blocks (64 rows each)
#define GRID   512         // <= 148 SMs * 4 resident blocks at <=64 regs: barrier-safe
#define ROWS_PER_BLK (B_ROWS / GRID)             // 16
#define TILE_BYTES   (ROWS_PER_BLK * D_DIM * 4)  // 16384
#define FLAG_STRIDE  32    // uints: 128B between consumer flags -> private L2 lines

// Scratch + barrier state (device globals: allocation-free rule, zero-init)
__device__ float g_partial[NPART * D_DIM];     // per-block column sums of prototypes
__device__ float g_p2[NPART];                  // per-block sum of squares
__device__ unsigned int g_count = 0;           // phase-1 arrivals
__device__ unsigned int g_done  = 0;           // exit counter (reset)
__device__ unsigned int g_ready[GRID * FLAG_STRIDE];  // 64KB: one line per block

__device__ __forceinline__ void cp_async16(void* smem_dst, const void* gmem_src) {
    unsigned int s;
    asm("{ .reg .u64 t; cvta.to.shared.u64 t, %1; cvt.u32.u64 %0, t; }"
        : "=r"(s) : "l"(smem_dst));
    asm volatile("cp.async.cg.shared.global [%0], [%1], 16;" :: "r"(s), "l"(gmem_src));
}

__device__ __forceinline__ unsigned int ld_acq_u32(const unsigned int* p) {
    unsigned int v;
    asm volatile("ld.acquire.gpu.global.u32 %0, [%1];" : "=r"(v) : "l"(p) : "memory");
    return v;
}

__device__ __forceinline__ void st_rel_u32(unsigned int* p, unsigned int v) {
    asm volatile("st.release.gpu.global.u32 [%0], %1;" :: "l"(p), "r"(v) : "memory");
}

__global__ void __launch_bounds__(256, 4)
som_fused(const float* __restrict__ x,
          const float* __restrict__ proto,
          float* __restrict__ out) {
    const int tid  = threadIdx.x;
    const int lane = tid & 31;
    const int warp = tid >> 5;
    const int blk  = blockIdx.x;

    __shared__ __align__(16) float sm_x[ROWS_PER_BLK * D_DIM];  // 16 KB x tile
    __shared__ __align__(16) float sm_grp[4 * D_DIM];           // row-group partials
    __shared__ float sm_p2g[8];
    __shared__ float sm_c;
    __shared__ unsigned int sm_role;   // 1 if this block is the last producer

    // ---- Step 0: issue async copy of this block's 16 x-rows IMMEDIATELY ------
    {
        const char* src = reinterpret_cast<const char*>(x) + (size_t)blk * TILE_BYTES;
#pragma unroll
        for (int r = 0; r < 4; ++r) {
            int chunk = tid + r * 256;               // 1024 chunks of 16B
            cp_async16(reinterpret_cast<char*>(sm_x) + chunk * 16,
                       src + chunk * 16);
        }
        asm volatile("cp.async.commit_group;");
    }

    if (tid == 0) sm_role = 0;

    // ---- Phase 1: prototype partials (blocks 0..15, 64 rows each) ------------
    if (blk < NPART) {
        const int c4   = tid & 63;                   // column group (4 floats)
        const int g    = tid >> 6;                   // 4 row-groups of 16 rows
        const int row0 = blk * (P_ROWS / NPART) + g * 16;

        float4 s = make_float4(0.f, 0.f, 0.f, 0.f);
        float sq = 0.f;
#pragma unroll
        for (int r = 0; r < 16; ++r) {               // MLP=16 float4 loads
            float4 v = *reinterpret_cast<const float4*>(
                proto + (row0 + r) * D_DIM + c4 * 4);
            s.x += v.x; s.y += v.y; s.z += v.z; s.w += v.w;
            sq  += v.x * v.x + v.y * v.y + v.z * v.z + v.w * v.w;
        }
        *reinterpret_cast<float4*>(&sm_grp[g * D_DIM + c4 * 4]) = s;

#pragma unroll
        for (int o = 16; o > 0; o >>= 1)
            sq += __shfl_down_sync(0xFFFFFFFFu, sq, o);
        if (lane == 0) sm_p2g[warp] = sq;
        __syncthreads();

        float col = sm_grp[tid] + sm_grp[D_DIM + tid] +
                    sm_grp[2 * D_DIM + tid] + sm_grp[3 * D_DIM + tid];
        g_partial[blk * D_DIM + tid] = col;
        if (tid == 0) {
            float p2 = 0.f;
#pragma unroll
            for (int i = 0; i < 8; ++i) p2 += sm_p2g[i];
            g_p2[blk] = p2;
        }

        // Every thread fences its own global stores, then one arrival.
        __threadfence();
        __syncthreads();
        if (tid == 0) {
            unsigned int old = atomicAdd(&g_count, 1u);
            if (old == NPART - 1) sm_role = 1;       // last producer -> broadcaster
        }
        __syncthreads();

        // ---- Broadcast: last producer sets every consumer's PRIVATE flag -----
        if (sm_role) {
            __threadfence();                         // acquire(count) + release(flags)
#pragma unroll
            for (int i = 0; i < GRID / 256; ++i)     // 2 flags per thread
                st_rel_u32(&g_ready[(tid + i * 256) * FLAG_STRIDE], 1u);
        }
    }

    // ---- Barrier: each block polls ONLY its own 128B-strided flag ------------
    if (tid == 0) {
        while (ld_acq_u32(&g_ready[blk * FLAG_STRIDE]) == 0u) { }
    }
    __syncthreads();

    // ---- Combine: every block, redundant, 16 KB L2-resident ------------------
    {
        float s = 0.f;
#pragma unroll
        for (int i = 0; i < NPART; ++i)
            s += __ldcg(&g_partial[i * D_DIM + tid]);   // column tid, coalesced

        __shared__ __align__(16) float sm_m2tmp[D_DIM];
        sm_m2tmp[tid] = s * (2.0f / (float)P_ROWS);

        if (warp == 0) {                 // all 32 lanes participate (R5 fix)
            float v = (lane < NPART) ? __ldcg(&g_p2[lane]) : 0.0f;
#pragma unroll
            for (int o = 16; o > 0; o >>= 1)
                v += __shfl_down_sync(0xFFFFFFFFu, v, o);
            if (lane == 0) sm_c = v * (1.0f / (float)P_ROWS);
        }
        __syncthreads();

        // ---- Phase 3: consume the prefetched x tile (2 rows per warp) --------
        const float c  = sm_c;
        const int  d0  = lane * 8;
        const float4 m0 = *reinterpret_cast<const float4*>(&sm_m2tmp[d0]);
        const float4 m1 = *reinterpret_cast<const float4*>(&sm_m2tmp[d0 + 4]);

        asm volatile("cp.async.wait_group 0;");
        __syncthreads();

        const int r0 = warp * 2;
        const float4* xr0 = reinterpret_cast<const float4*>(&sm_x[r0 * D_DIM + d0]);
        const float4* xr1 = reinterpret_cast<const float4*>(&sm_x[(r0 + 1) * D_DIM + d0]);

        float4 a0 = xr0[0], a1 = xr0[1];
        float4 b0 = xr1[0], b1 = xr1[1];

        float acc0, acc1;
        acc0  = a0.x * (a0.x - m0.x);  acc1  = b0.x * (b0.x - m0.x);
        acc0 += a0.y * (a0.y - m0.y);  acc1 += b0.y * (b0.y - m0.y);
        acc0 += a0.z * (a0.z - m0.z);  acc1 += b0.z * (b0.z - m0.z);
        acc0 += a0.w * (a0.w - m0.w);  acc1 += b0.w * (b0.w - m0.w);
        acc0 += a1.x * (a1.x - m1.x);  acc1 += b1.x * (b1.x - m1.x);
        acc0 += a1.y * (a1.y - m1.y);  acc1 += b1.y * (b1.y - m1.y);
        acc0 += a1.z * (a1.z - m1.z);  acc1 += b1.z * (b1.z - m1.z);
        acc0 += a1.w * (a1.w - m1.w);  acc1 += b1.w * (b1.w - m1.w);

#pragma unroll
        for (int o = 16; o > 0; o >>= 1) {
            acc0 += __shfl_down_sync(0xFFFFFFFFu, acc0, o);
            acc1 += __shfl_down_sync(0xFFFFFFFFu, acc1, o);
        }

        const int rowg = blk * ROWS_PER_BLK + r0;
        if (lane == 0) {
            out[rowg]     = acc0 + c;
            out[rowg + 1] = acc1 + c;
        }
    }

    // ---- Reset barrier state for the next graph replay -----------------------
    __syncthreads();
    __shared__ unsigned int sm_last;
    if (tid == 0) {
        unsigned int d = atomicAdd(&g_done, 1u);
        sm_last = (d == GRID - 1) ? 1u : 0u;
    }
    __syncthreads();
    if (sm_last) {                       // last block out: whole block resets
#pragma unroll
        for (int i = 0; i < GRID / 256; ++i)
            g_ready[(tid + i * 256) * FLAG_STRIDE] = 0u;
        if (tid == 0) {
            g_count = 0;
            g_done  = 0;
        }
        __threadfence();
    }
}

extern "C" void kernel_launch(void* const* d_in, const int* in_sizes, int n_in,
                              void* d_out, int out_size) {
    const float* x     = (const float*)d_in[0];  // (8192, 256) float32
    const float* proto = (const float*)d_in[1];  // (1024, 256) float32
    float* out = (float*)d_out;                  // (8192,) float32

    som_fused<<<GRID, 256>>>(x, proto, out);
}

// round 9
// speedup vs baseline: 1.0364x; 1.0364x over previous
#include <cuda_runtime.h>

#define B_ROWS 8192
#define P_ROWS 1024
#define D_DIM  256
#define NPART  16          // prototype partial-reduction blocks (64 rows each)
#define GRID   512         // <= 148 SMs * 4 resident blocks at <=64 regs: barrier-safe
#define ROWS_PER_BLK (B_ROWS / GRID)             // 16
#define TILE_BYTES   (ROWS_PER_BLK * D_DIM * 4)  // 16384
#define FLAG_STRIDE  32    // uints: 128B between flags -> private L2 line per block

// Scratch + barrier state (device globals: allocation-free rule, zero-init)
__device__ float g_partial[NPART * D_DIM];     // per-block column sums of prototypes
__device__ float g_p2[NPART];                  // per-block sum of squares
__device__ unsigned int g_count = 0;           // phase-1 arrivals (16 adds total)
__device__ unsigned int g_ready[GRID * FLAG_STRIDE];  // one private line per block

__device__ __forceinline__ void cp_async16(void* smem_dst, const void* gmem_src) {
    unsigned int s;
    asm("{ .reg .u64 t; cvta.to.shared.u64 t, %1; cvt.u32.u64 %0, t; }"
        : "=r"(s) : "l"(smem_dst));
    asm volatile("cp.async.cg.shared.global [%0], [%1], 16;" :: "r"(s), "l"(gmem_src));
}

__device__ __forceinline__ unsigned int ld_acq_u32(const unsigned int* p) {
    unsigned int v;
    asm volatile("ld.acquire.gpu.global.u32 %0, [%1];" : "=r"(v) : "l"(p) : "memory");
    return v;
}

__device__ __forceinline__ void st_rel_u32(unsigned int* p, unsigned int v) {
    asm volatile("st.release.gpu.global.u32 [%0], %1;" :: "l"(p), "r"(v) : "memory");
}

__device__ __forceinline__ void issue_x_tile(const float* x, int blk, float* sm_x,
                                             int tid) {
    const char* src = reinterpret_cast<const char*>(x) + (size_t)blk * TILE_BYTES;
#pragma unroll
    for (int r = 0; r < 4; ++r) {
        int chunk = tid + r * 256;                   // 1024 chunks of 16B
        cp_async16(reinterpret_cast<char*>(sm_x) + chunk * 16, src + chunk * 16);
    }
    asm volatile("cp.async.commit_group;");
}

__global__ void __launch_bounds__(256, 4)
som_fused(const float* __restrict__ x,
          const float* __restrict__ proto,
          float* __restrict__ out) {
    const int tid  = threadIdx.x;
    const int lane = tid & 31;
    const int warp = tid >> 5;
    const int blk  = blockIdx.x;

    __shared__ __align__(16) float sm_x[ROWS_PER_BLK * D_DIM];  // 16 KB x tile
    __shared__ __align__(16) float sm_grp[4 * D_DIM];           // row-group partials
    __shared__ float sm_p2g[8];
    __shared__ float sm_c;
    __shared__ unsigned int sm_role;   // 1 if this block is the broadcaster

    if (tid == 0) sm_role = 0;

    if (blk < NPART) {
        // ---- Producer: proto loads FIRST (ahead of prefetch in L1tex queue) --
        const int c4   = tid & 63;                   // column group (4 floats)
        const int g    = tid >> 6;                   // 4 row-groups of 16 rows
        const int row0 = blk * (P_ROWS / NPART) + g * 16;

        float4 s = make_float4(0.f, 0.f, 0.f, 0.f);
        float sq = 0.f;
#pragma unroll
        for (int r = 0; r < 16; ++r) {               // MLP=16 float4 loads
            float4 v = *reinterpret_cast<const float4*>(
                proto + (row0 + r) * D_DIM + c4 * 4);
            s.x += v.x; s.y += v.y; s.z += v.z; s.w += v.w;
            sq  += v.x * v.x + v.y * v.y + v.z * v.z + v.w * v.w;
        }

        // now the x-tile prefetch (overlaps the reduce/barrier below)
        issue_x_tile(x, blk, sm_x, tid);

        *reinterpret_cast<float4*>(&sm_grp[g * D_DIM + c4 * 4]) = s;
#pragma unroll
        for (int o = 16; o > 0; o >>= 1)
            sq += __shfl_down_sync(0xFFFFFFFFu, sq, o);
        if (lane == 0) sm_p2g[warp] = sq;
        __syncthreads();

        float col = sm_grp[tid] + sm_grp[D_DIM + tid] +
                    sm_grp[2 * D_DIM + tid] + sm_grp[3 * D_DIM + tid];
        g_partial[blk * D_DIM + tid] = col;
        if (tid == 0) {
            float p2 = 0.f;
#pragma unroll
            for (int i = 0; i < 8; ++i) p2 += sm_p2g[i];
            g_p2[blk] = p2;
        }

        // Every thread fences its own global stores, then one arrival.
        __threadfence();
        __syncthreads();
        if (tid == 0) {
            unsigned int old = atomicAdd(&g_count, 1u);
            if (old == NPART - 1) sm_role = 1;       // last producer broadcasts
        }
        __syncthreads();

        if (sm_role) {
            // Sole remaining accessor of g_count: reset it here (no exit pass).
            if (tid == 0) g_count = 0;
            __threadfence();                         // partials visible pre-flag
#pragma unroll
            for (int i = 0; i < GRID / 256; ++i)     // 2 flags per thread
                st_rel_u32(&g_ready[(tid + i * 256) * FLAG_STRIDE], 1u);
        }
    } else {
        // ---- Consumer: just start the x-tile prefetch ------------------------
        issue_x_tile(x, blk, sm_x, tid);
    }

    // ---- Barrier: poll ONLY own private flag; self-reset on pass -------------
    // (self-reset replaces the 512-way g_done exit atomic that serialized
    //  ~27cyc/op at one LTS address into a multi-microsecond kernel tail)
    if (tid == 0) {
        while (ld_acq_u32(&g_ready[blk * FLAG_STRIDE]) == 0u) { }
        g_ready[blk * FLAG_STRIDE] = 0u;             // private line, no contention
    }
    __syncthreads();

    // ---- Combine: every block, redundant, 16 KB L2-resident ------------------
    {
        float s = 0.f;
#pragma unroll
        for (int i = 0; i < NPART; ++i)
            s += __ldcg(&g_partial[i * D_DIM + tid]);   // column tid, coalesced

        __shared__ __align__(16) float sm_m2tmp[D_DIM];
        sm_m2tmp[tid] = s * (2.0f / (float)P_ROWS);

        if (warp == 0) {                 // all 32 lanes participate (R5 fix)
            float v = (lane < NPART) ? __ldcg(&g_p2[lane]) : 0.0f;
#pragma unroll
            for (int o = 16; o > 0; o >>= 1)
                v += __shfl_down_sync(0xFFFFFFFFu, v, o);
            if (lane == 0) sm_c = v * (1.0f / (float)P_ROWS);
        }
        __syncthreads();

        // ---- Phase 3: consume the prefetched x tile (2 rows per warp) --------
        const float c  = sm_c;
        const int  d0  = lane * 8;
        const float4 m0 = *reinterpret_cast<const float4*>(&sm_m2tmp[d0]);
        const float4 m1 = *reinterpret_cast<const float4*>(&sm_m2tmp[d0 + 4]);

        asm volatile("cp.async.wait_group 0;");
        __syncthreads();

        const int r0 = warp * 2;
        const float4* xr0 = reinterpret_cast<const float4*>(&sm_x[r0 * D_DIM + d0]);
        const float4* xr1 = reinterpret_cast<const float4*>(&sm_x[(r0 + 1) * D_DIM + d0]);

        float4 a0 = xr0[0], a1 = xr0[1];
        float4 b0 = xr1[0], b1 = xr1[1];

        float acc0, acc1;
        acc0  = a0.x * (a0.x - m0.x);  acc1  = b0.x * (b0.x - m0.x);
        acc0 += a0.y * (a0.y - m0.y);  acc1 += b0.y * (b0.y - m0.y);
        acc0 += a0.z * (a0.z - m0.z);  acc1 += b0.z * (b0.z - m0.z);
        acc0 += a0.w * (a0.w - m0.w);  acc1 += b0.w * (b0.w - m0.w);
        acc0 += a1.x * (a1.x - m1.x);  acc1 += b1.x * (b1.x - m1.x);
        acc0 += a1.y * (a1.y - m1.y);  acc1 += b1.y * (b1.y - m1.y);
        acc0 += a1.z * (a1.z - m1.z);  acc1 += b1.z * (b1.z - m1.z);
        acc0 += a1.w * (a1.w - m1.w);  acc1 += b1.w * (b1.w - m1.w);

#pragma unroll
        for (int o = 16; o > 0; o >>= 1) {
            acc0 += __shfl_down_sync(0xFFFFFFFFu, acc0, o);
            acc1 += __shfl_down_sync(0xFFFFFFFFu, acc1, o);
        }

        const int rowg = blk * ROWS_PER_BLK + r0;
        if (lane == 0) {
            out[rowg]     = acc0 + c;
            out[rowg + 1] = acc1 + c;
        }
    }
    // No exit counter, no reset pass: kernel ends here.
}

extern "C" void kernel_launch(void* const* d_in, const int* in_sizes, int n_in,
                              void* d_out, int out_size) {
    const float* x     = (const float*)d_in[0];  // (8192, 256) float32
    const float* proto = (const float*)d_in[1];  // (1024, 256) float32
    float* out = (float*)d_out;                  // (8192,) float32

    som_fused<<<GRID, 256>>>(x, proto, out);
}

// round 10
// speedup vs baseline: 1.1633x; 1.1224x over previous
#include <cuda_runtime.h>

#define B_ROWS 8192
#define P_ROWS 1024
#define D_DIM  256
#define NPART  32              // K1 blocks; 32 proto rows each
#define G3     256             // K3 blocks
#define T3     512             // K3 threads: 16 warps, 2 rows/warp -> 32 rows/block

// Inter-kernel scratch (allocation-free rule: device globals).
// Ordering between K1 writes and K3 reads is provided by the kernel
// boundary / griddepcontrol.wait -- no fences, no flags, no atomics.
__device__ float g_partial[NPART * D_DIM];   // per-block column sums of prototypes
__device__ float g_p2[NPART];                // per-block sum of squares

// ---------------------------------------------------------------------------
// K1: prototype stats. 32 blocks x 256 thr, 32 rows/block, 8 float4 per thread.
// Signals dependent launch immediately so K3 runs concurrently.
// ---------------------------------------------------------------------------
__global__ void __launch_bounds__(256) k1_proto(const float* __restrict__ proto) {
    asm volatile("griddepcontrol.launch_dependents;");

    const int tid  = threadIdx.x;
    const int lane = tid & 31;
    const int warp = tid >> 5;
    const int c4   = tid & 63;               // float4 column group
    const int g    = tid >> 6;               // 4 row-groups of 8 rows
    const int row0 = blockIdx.x * (P_ROWS / NPART) + g * 8;

    __shared__ __align__(16) float sg[4 * D_DIM];
    __shared__ float sp[8];

    float4 s = make_float4(0.f, 0.f, 0.f, 0.f);
    float sq = 0.f;
#pragma unroll
    for (int r = 0; r < 8; ++r) {            // 8 independent float4 loads (MLP=8)
        float4 v = *reinterpret_cast<const float4*>(
            proto + (row0 + r) * D_DIM + c4 * 4);
        s.x += v.x; s.y += v.y; s.z += v.z; s.w += v.w;
        sq  += v.x * v.x + v.y * v.y + v.z * v.z + v.w * v.w;
    }
    *reinterpret_cast<float4*>(&sg[g * D_DIM + c4 * 4]) = s;

#pragma unroll
    for (int o = 16; o > 0; o >>= 1)
        sq += __shfl_down_sync(0xFFFFFFFFu, sq, o);
    if (lane == 0) sp[warp] = sq;
    __syncthreads();

    // column tid over the 4 row-groups
    g_partial[blockIdx.x * D_DIM + tid] =
        sg[tid] + sg[D_DIM + tid] + sg[2 * D_DIM + tid] + sg[3 * D_DIM + tid];
    if (tid == 0) {
        float p2 = 0.f;
#pragma unroll
        for (int i = 0; i < 8; ++i) p2 += sp[i];
        g_p2[blockIdx.x] = p2;
    }
}

// ---------------------------------------------------------------------------
// K3: stream x. 256 blocks x 512 thr. Loads x into registers BEFORE waiting on
// K1 (x is a pure input), so the 8MB stream overlaps K1 under PDL.
// ---------------------------------------------------------------------------
__global__ void __launch_bounds__(T3) k3_main(const float* __restrict__ x,
                                             float* __restrict__ out) {
    const int tid  = threadIdx.x;
    const int lane = tid & 31;
    const int warp = tid >> 5;
    const int d0   = lane * 8;
    const int row0 = blockIdx.x * 32 + warp * 2;   // 2 rows per warp

    // ---- x loads first: 4 independent LDG.128 per thread ----
    const float4* xr0 = reinterpret_cast<const float4*>(x + row0 * D_DIM + d0);
    const float4* xr1 = reinterpret_cast<const float4*>(x + (row0 + 1) * D_DIM + d0);
    float4 a0 = xr0[0], a1 = xr0[1];
    float4 b0 = xr1[0], b1 = xr1[1];

    // ---- now require K1's results (PDL: blocks until K1 fully complete) ----
    asm volatile("griddepcontrol.wait;" ::: "memory");

    __shared__ float smp[2][D_DIM];
    __shared__ __align__(16) float sm2[D_DIM];
    __shared__ float smc;

    // combine: 512 threads split the 32 partial rows into 2 halves of 16
    {
        const int col  = tid & 255;
        const int half = tid >> 8;
        float s = 0.f;
#pragma unroll
        for (int i = 0; i < 16; ++i)
            s += g_partial[(half * 16 + i) * D_DIM + col];
        smp[half][col] = s;
    }
    if (warp == 0) {                         // 32 lanes <-> 32 p2 partials
        float v = g_p2[lane];
#pragma unroll
        for (int o = 16; o > 0; o >>= 1)
            v += __shfl_down_sync(0xFFFFFFFFu, v, o);
        if (lane == 0) smc = v * (1.0f / (float)P_ROWS);
    }
    __syncthreads();
    if (tid < D_DIM)
        sm2[tid] = (smp[0][tid] + smp[1][tid]) * (2.0f / (float)P_ROWS);
    __syncthreads();

    const float  c  = smc;
    const float4 m0 = *reinterpret_cast<const float4*>(&sm2[d0]);
    const float4 m1 = *reinterpret_cast<const float4*>(&sm2[d0 + 4]);

    float acc0, acc1;
    acc0  = a0.x * (a0.x - m0.x);  acc1  = b0.x * (b0.x - m0.x);
    acc0 += a0.y * (a0.y - m0.y);  acc1 += b0.y * (b0.y - m0.y);
    acc0 += a0.z * (a0.z - m0.z);  acc1 += b0.z * (b0.z - m0.z);
    acc0 += a0.w * (a0.w - m0.w);  acc1 += b0.w * (b0.w - m0.w);
    acc0 += a1.x * (a1.x - m1.x);  acc1 += b1.x * (b1.x - m1.x);
    acc0 += a1.y * (a1.y - m1.y);  acc1 += b1.y * (b1.y - m1.y);
    acc0 += a1.z * (a1.z - m1.z);  acc1 += b1.z * (b1.z - m1.z);
    acc0 += a1.w * (a1.w - m1.w);  acc1 += b1.w * (b1.w - m1.w);

#pragma unroll
    for (int o = 16; o > 0; o >>= 1) {
        acc0 += __shfl_down_sync(0xFFFFFFFFu, acc0, o);
        acc1 += __shfl_down_sync(0xFFFFFFFFu, acc1, o);
    }
    if (lane == 0) {
        out[row0]     = acc0 + c;
        out[row0 + 1] = acc1 + c;
    }
}

extern "C" void kernel_launch(void* const* d_in, const int* in_sizes, int n_in,
                              void* d_out, int out_size) {
    const float* x     = (const float*)d_in[0];  // (8192, 256) float32
    const float* proto = (const float*)d_in[1];  // (1024, 256) float32
    float* out = (float*)d_out;                  // (8192,) float32

    k1_proto<<<NPART, 256>>>(proto);

    // K3 with programmatic dependent launch: overlaps K1; falls back to
    // normal stream serialization (still correct) if PDL is unavailable.
    cudaLaunchConfig_t cfg = {};
    cfg.gridDim  = dim3(G3, 1, 1);
    cfg.blockDim = dim3(T3, 1, 1);
    cfg.dynamicSmemBytes = 0;
    cudaLaunchAttribute attr[1];
    attr[0].id = cudaLaunchAttributeProgrammaticStreamSerialization;
    attr[0].val.programmaticStreamSerializationAllowed = 1;
    cfg.attrs    = attr;
    cfg.numAttrs = 1;
    cudaLaunchKernelEx(&cfg, k3_main, x, out);
}